// round 4
// baseline (speedup 1.0000x reference)
#include <cuda_runtime.h>
#include <cstdint>

typedef unsigned long long u64;

#define BB   256
#define TT   2048
#define HH   256
#define PP   24
#define BC   2            // batch rows per CTA
#define NCTA (BB/BC)      // 128
#define NTHR 256
#define NREG4 32          // float4 chunks of W row kept in registers (128 floats)
#define NSM4  32          // float4 chunks of W row kept in SMEM     (128 floats)
#define H4   (HH/4)       // 64

// packed f32x2 FMA: d = a*b + d (elementwise on 2 packed floats)
__device__ __forceinline__ void fma2(u64 &d, u64 a, u64 b) {
    asm("fma.rn.f32x2 %0, %1, %2, %0;" : "+l"(d) : "l"(a), "l"(b));
}
__device__ __forceinline__ float2 unpk(u64 v) {
    float2 r; asm("mov.b64 {%0, %1}, %2;" : "=f"(r.x), "=f"(r.y) : "l"(v)); return r;
}

// SMEM layout (dynamic):
//   [0, 128KB)              sW[c][i]  : chunk (NREG4+c) of W row i (ulonglong2)
//   [128KB, 132KB)          h double buffer [2][BC][H4] float4
//   [132KB, 148KB)          x stage   [BC][TT] floats
#define SW_BYTES   ((size_t)NSM4 * HH * 16)
#define HB_BYTES   ((size_t)2 * BC * H4 * 16)
#define X_BYTES    ((size_t)BC * TT * 4)
#define SMEM_TOTAL (SW_BYTES + HB_BYTES + X_BYTES)

__global__ void __launch_bounds__(NTHR, 1)
rnn_persistent_kernel(const float* __restrict__ x,
                      const float* __restrict__ W_ih,
                      const float* __restrict__ W_hh,
                      const float* __restrict__ b_ih,
                      const float* __restrict__ b_hh,
                      const float* __restrict__ W_out,
                      const float* __restrict__ b_out,
                      float* __restrict__ out)
{
    extern __shared__ char smem[];
    ulonglong2* sW   = (ulonglong2*)smem;
    ulonglong2* hbuf = (ulonglong2*)(smem + SW_BYTES);
    float*      sx   = (float*)(smem + SW_BYTES + HB_BYTES);

    const int i  = threadIdx.x;      // output row owned by this thread
    const int b0 = blockIdx.x * BC;  // first batch row of this CTA

    // ---- Prologue: load my W_hh row (reg part + smem part), per-row constants
    const ulonglong2* wrow = (const ulonglong2*)(W_hh + (size_t)i * HH);
    ulonglong2 wreg[NREG4];
#pragma unroll
    for (int c = 0; c < NREG4; c++) wreg[c] = wrow[c];
#pragma unroll
    for (int c = 0; c < NSM4; c++)  sW[c * HH + i] = wrow[NREG4 + c];

    // stage x[b0:b0+BC, :] into smem (coalesced float4)
    {
        const float4* xg = (const float4*)(x + (size_t)b0 * TT);
        float4*       xs = (float4*)sx;
        const int n4 = BC * TT / 4;   // 1024
#pragma unroll
        for (int k = i; k < n4; k += NTHR) xs[k] = xg[k];
    }

    const float wih  = W_ih[i];
    const float bias = b_ih[i] + b_hh[i];

    // zero h buffer 0 (BC*H4 = 128 ulonglong2 entries)
    if (i < BC * H4) { ulonglong2 z; z.x = 0ull; z.y = 0ull; hbuf[i] = z; }
    __syncthreads();

    const float* xb0 = sx;
    const float* xb1 = sx + TT;

    int rb = 0;  // read buffer index
    for (int t = 0; t < TT; t++) {
        const ulonglong2* h0 = hbuf + rb * (BC * H4);  // h for batch b0 (broadcast)
        const ulonglong2* h1 = h0 + H4;                // h for batch b1

        // 4 independent packed accumulator chains (even/odd pairs x 2 batches)
        u64 a00 = 0ull, a01 = 0ull, a10 = 0ull, a11 = 0ull;

#pragma unroll
        for (int c = 0; c < NREG4; c++) {
            ulonglong2 hv0 = h0[c];
            ulonglong2 hv1 = h1[c];
            ulonglong2 wv  = wreg[c];
            fma2(a00, hv0.x, wv.x); fma2(a01, hv0.y, wv.y);
            fma2(a10, hv1.x, wv.x); fma2(a11, hv1.y, wv.y);
        }
#pragma unroll
        for (int c = 0; c < NSM4; c++) {
            ulonglong2 wv  = sW[c * HH + i];   // lanes consecutive -> conflict-free
            ulonglong2 hv0 = h0[NREG4 + c];
            ulonglong2 hv1 = h1[NREG4 + c];
            fma2(a00, hv0.x, wv.x); fma2(a01, hv0.y, wv.y);
            fma2(a10, hv1.x, wv.x); fma2(a11, hv1.y, wv.y);
        }

        float2 f00 = unpk(a00), f01 = unpk(a01), f10 = unpk(a10), f11 = unpk(a11);
        float s0 = (f00.x + f00.y) + (f01.x + f01.y);
        float s1 = (f10.x + f10.y) + (f11.x + f11.y);

        float pre0 = fmaf(xb0[t], wih, bias) + s0;
        float pre1 = fmaf(xb1[t], wih, bias) + s1;
        float hn0 = tanhf(pre0);
        float hn1 = tanhf(pre1);

        const int wbuf = rb ^ 1;
        float* hw = (float*)(hbuf + wbuf * (BC * H4));
        hw[i]      = hn0;   // batch b0, element i (consecutive -> conflict-free)
        hw[HH + i] = hn1;   // batch b1
        __syncthreads();    // single barrier per step (double-buffered h)
        rb = wbuf;
    }

    // ---- Epilogue: out[b,p] = h_T[b,:] . W_out[p,:] + b_out[p]
    const float* hfin = (const float*)(hbuf + rb * (BC * H4));
    if (i < BC * PP) {
        const int bb = i / PP;
        const int p  = i % PP;
        const float* hr = hfin + bb * HH;
        const float* wo = W_out + (size_t)p * HH;
        float acc = b_out[p];
#pragma unroll 8
        for (int k = 0; k < HH; k++) acc = fmaf(hr[k], wo[k], acc);
        out[(size_t)(b0 + bb) * PP + p] = acc;
    }
}

extern "C" void kernel_launch(void* const* d_in, const int* in_sizes, int n_in,
                              void* d_out, int out_size)
{
    const float* x     = (const float*)d_in[0];
    const float* W_ih  = (const float*)d_in[1];
    const float* W_hh  = (const float*)d_in[2];
    const float* b_ih  = (const float*)d_in[3];
    const float* b_hh  = (const float*)d_in[4];
    const float* W_out = (const float*)d_in[5];
    const float* b_out = (const float*)d_in[6];
    float* out = (float*)d_out;

    cudaFuncSetAttribute(rnn_persistent_kernel,
                         cudaFuncAttributeMaxDynamicSharedMemorySize, (int)SMEM_TOTAL);
    rnn_persistent_kernel<<<NCTA, NTHR, SMEM_TOTAL>>>(x, W_ih, W_hh, b_ih, b_hh,
                                                      W_out, b_out, out);
}

// round 6
// speedup vs baseline: 1.4594x; 1.4594x over previous
#include <cuda_runtime.h>
#include <cstdint>

typedef unsigned long long u64;

#define BB   256
#define TT   2048
#define HH   256
#define PP   24
#define BC   2              // batch rows per CTA
#define NCTA (BB/BC)        // 128
#define NTHR 512
#define NREGC 20            // W float4-chunks kept in registers per thread (80 floats)
#define NSMC  12            // W float4-chunks kept in smem per thread      (48 floats)

// packed f32x2 FMA: d = a*b + d
__device__ __forceinline__ void fma2(u64 &d, u64 a, u64 b) {
    asm("fma.rn.f32x2 %0, %1, %2, %0;" : "+l"(d) : "l"(a), "l"(b));
}
__device__ __forceinline__ float2 unpk(u64 v) {
    float2 r; asm("mov.b64 {%0, %1}, %2;" : "=f"(r.x), "=f"(r.y) : "l"(v)); return r;
}

// SMEM layout:
//  [0, 96K)        sW[c][t] : W chunk c of thread t (ulonglong2), c < NSMC
//  [96K, 100K)     h double buffer [2][BC][HH] floats, swizzled intra-row
//  [100K, 116K)    x stage [BC][TT]
#define SW_BYTES   ((size_t)NSMC * NTHR * 16)
#define HB_BYTES   ((size_t)2 * BC * HH * 4)
#define X_BYTES    ((size_t)BC * TT * 4)
#define SMEM_TOTAL (SW_BYTES + HB_BYTES + X_BYTES)

// hidden index col -> swizzled storage position within a 256-float row
__device__ __forceinline__ int hswz(int col) {
    return (((col >> 2) & 7) * 8 + (col >> 5)) * 4 + (col & 3);
}

__global__ void __launch_bounds__(NTHR, 1)
rnn_persistent_kernel(const float* __restrict__ x,
                      const float* __restrict__ W_ih,
                      const float* __restrict__ W_hh,
                      const float* __restrict__ b_ih,
                      const float* __restrict__ b_hh,
                      const float* __restrict__ W_out,
                      const float* __restrict__ b_out,
                      float* __restrict__ out)
{
    extern __shared__ char smem[];
    ulonglong2* sW   = (ulonglong2*)smem;
    float*      hbuf = (float*)(smem + SW_BYTES);
    float*      sx   = (float*)(smem + SW_BYTES + HB_BYTES);

    const int t  = threadIdx.x;
    const int g  = t >> 3;      // row group: rows 4g..4g+3
    const int k  = t & 7;       // column strip: cols 32k..32k+31
    const int b0 = blockIdx.x * BC;

    // ---- Prologue: load W chunks. Thread (g,k) needs rows 4g+j, float4 chunks
    // at row-local float4 index k*8 + c, c in [0,8).
    const ulonglong2* Wv = (const ulonglong2*)W_hh;   // row stride = 64 float4
    ulonglong2 wr[NREGC];
#pragma unroll
    for (int c = 0; c < 8; c++) wr[c]      = Wv[(size_t)(4*g + 0) * 64 + k*8 + c];
#pragma unroll
    for (int c = 0; c < 8; c++) wr[8 + c]  = Wv[(size_t)(4*g + 1) * 64 + k*8 + c];
#pragma unroll
    for (int c = 0; c < 4; c++) wr[16 + c] = Wv[(size_t)(4*g + 2) * 64 + k*8 + c];
#pragma unroll
    for (int c = 0; c < 4; c++) sW[c * NTHR + t]       = Wv[(size_t)(4*g + 2) * 64 + k*8 + 4 + c];
#pragma unroll
    for (int c = 0; c < 8; c++) sW[(4 + c) * NTHR + t] = Wv[(size_t)(4*g + 3) * 64 + k*8 + c];

    // lane-owned output after reduction: row 4g + (k>>1), batch (k&1)
    const int jsel  = k >> 1;
    const int bsel  = k & 1;
    const int myrow = 4*g + jsel;
    const float bias_l = b_ih[myrow] + b_hh[myrow];
    const float wih_l  = W_ih[myrow];
    const int   wpos   = bsel * HH + hswz(myrow);   // write slot in h buffer

    // stage x[b0:b0+BC, :] into smem (coalesced float4)
    {
        const float4* xg = (const float4*)(x + (size_t)b0 * TT);
        float4*       xs = (float4*)sx;
        for (int q = t; q < BC * TT / 4; q += NTHR) xs[q] = xg[q];
    }
    // zero h buffer 0 (BC*HH = 512 floats)
    hbuf[t] = 0.0f;
    __syncthreads();

    const bool hb4 = (k & 4) != 0;
    const bool hb2 = (k & 2) != 0;
    const bool hb1 = (k & 1) != 0;

    int rb = 0;
    for (int ts = 0; ts < TT; ts++) {
        const ulonglong2* hr = (const ulonglong2*)(hbuf + rb * (BC * HH));
        // h float4 index for (batch b, chunk c): b*64 + c*8 + k  (swizzled layout)

        u64 a0=0ull,a1=0ull,a2=0ull,a3=0ull,a4=0ull,a5=0ull,a6=0ull,a7=0ull;
        // a[m], m = j*2 + b

#pragma unroll
        for (int c = 0; c < 8; c++) {
            ulonglong2 h0 = hr[c*8 + k];
            ulonglong2 h1 = hr[64 + c*8 + k];
            ulonglong2 w0 = wr[c];
            ulonglong2 w1 = wr[8 + c];
            ulonglong2 w2 = (c < 4) ? wr[16 + c] : sW[(c - 4) * NTHR + t];
            ulonglong2 w3 = sW[(4 + c) * NTHR + t];
            fma2(a0, h0.x, w0.x); fma2(a0, h0.y, w0.y);
            fma2(a1, h1.x, w0.x); fma2(a1, h1.y, w0.y);
            fma2(a2, h0.x, w1.x); fma2(a2, h0.y, w1.y);
            fma2(a3, h1.x, w1.x); fma2(a3, h1.y, w1.y);
            fma2(a4, h0.x, w2.x); fma2(a4, h0.y, w2.y);
            fma2(a5, h1.x, w2.x); fma2(a5, h1.y, w2.y);
            fma2(a6, h0.x, w3.x); fma2(a6, h0.y, w3.y);
            fma2(a7, h1.x, w3.x); fma2(a7, h1.y, w3.y);
        }

        float2 f;
        f = unpk(a0); float s0 = f.x + f.y;
        f = unpk(a1); float s1 = f.x + f.y;
        f = unpk(a2); float s2 = f.x + f.y;
        f = unpk(a3); float s3 = f.x + f.y;
        f = unpk(a4); float s4 = f.x + f.y;
        f = unpk(a5); float s5 = f.x + f.y;
        f = unpk(a6); float s6 = f.x + f.y;
        f = unpk(a7); float s7 = f.x + f.y;

        // recursive-halving exchange over the 8-lane column groups:
        // lane k ends with full sum for m = k  (row 4g+(k>>1), batch k&1)
        float t0 = hb4 ? s4 : s0,  u0 = hb4 ? s0 : s4;
        float t1 = hb4 ? s5 : s1,  u1 = hb4 ? s1 : s5;
        float t2 = hb4 ? s6 : s2,  u2 = hb4 ? s2 : s6;
        float t3 = hb4 ? s7 : s3,  u3 = hb4 ? s3 : s7;
        t0 += __shfl_xor_sync(0xffffffffu, u0, 4);
        t1 += __shfl_xor_sync(0xffffffffu, u1, 4);
        t2 += __shfl_xor_sync(0xffffffffu, u2, 4);
        t3 += __shfl_xor_sync(0xffffffffu, u3, 4);

        float p0 = hb2 ? t2 : t0,  q0 = hb2 ? t0 : t2;
        float p1 = hb2 ? t3 : t1,  q1 = hb2 ? t1 : t3;
        p0 += __shfl_xor_sync(0xffffffffu, q0, 2);
        p1 += __shfl_xor_sync(0xffffffffu, q1, 2);

        float vk = hb1 ? p1 : p0,  vs = hb1 ? p0 : p1;
        vk += __shfl_xor_sync(0xffffffffu, vs, 1);

        float pre = vk + fmaf(sx[bsel * TT + ts], wih_l, bias_l);
        float hn  = tanhf(pre);

        const int wb = rb ^ 1;
        hbuf[wb * (BC * HH) + wpos] = hn;
        __syncthreads();
        rb = wb;
    }

    // ---- Epilogue: out[b,p] = h_T[b,:] . W_out[p,:] + b_out[p]
    if (t < BC * PP) {
        const int bb = t / PP;
        const int p  = t % PP;
        const float* hf = hbuf + rb * (BC * HH) + bb * HH;
        const float* wo = W_out + (size_t)p * HH;
        float acc = b_out[p];
#pragma unroll 8
        for (int col = 0; col < HH; col++)
            acc = fmaf(hf[hswz(col)], wo[col], acc);
        out[(size_t)(b0 + bb) * PP + p] = acc;
    }
}

extern "C" void kernel_launch(void* const* d_in, const int* in_sizes, int n_in,
                              void* d_out, int out_size)
{
    const float* x     = (const float*)d_in[0];
    const float* W_ih  = (const float*)d_in[1];
    const float* W_hh  = (const float*)d_in[2];
    const float* b_ih  = (const float*)d_in[3];
    const float* b_hh  = (const float*)d_in[4];
    const float* W_out = (const float*)d_in[5];
    const float* b_out = (const float*)d_in[6];
    float* out = (float*)d_out;

    cudaFuncSetAttribute(rnn_persistent_kernel,
                         cudaFuncAttributeMaxDynamicSharedMemorySize, (int)SMEM_TOTAL);
    rnn_persistent_kernel<<<NCTA, NTHR, SMEM_TOTAL>>>(x, W_ih, W_hh, b_ih, b_hh,
                                                      W_out, b_out, out);
}